// round 7
// baseline (speedup 1.0000x reference)
#include <cuda_runtime.h>

#define V_TOTAL     8192
#define NODE_DIM    256
#define MAX_DEG     64
#define NUM_SAMPLES 16
#define GROUP_DIM   4
#define N_NODES     100000

#define BM 64
#define BN 128
#define BK 32
#define NT 128
#define NCHUNK (NODE_DIM / BK)   // 8
#define ADST 132                 // 2*BM + 4: 16B-aligned rows for LDS.128

// Scratch for linear-branch result L = features[ids] @ W + b   (8 MB)
__device__ float g_L[V_TOTAL * NODE_DIM];

// Packed fp32x2 FMA (Blackwell): d = a*b + d, two fp32 lanes per instruction.
#define FMA2(d, a, b) \
    asm("fma.rn.f32x2 %0, %1, %2, %0;" : "+l"(d) : "l"(a), "l"(b))

static __device__ __forceinline__ float2 unpack_f32x2(unsigned long long v) {
    float2 r;
    asm("mov.b64 {%0, %1}, %2;" : "=f"(r.x), "=f"(r.y) : "l"(v));
    return r;
}

#define CP_ASYNC16(smem_u32, gptr) \
    asm volatile("cp.async.cg.shared.global [%0], [%1], 16;" \
                 :: "r"(smem_u32), "l"(gptr))
#define CP_COMMIT()  asm volatile("cp.async.commit_group;")
#define CP_WAIT0()   asm volatile("cp.async.wait_group 0;")

// ---------------------------------------------------------------------------
// Kernel 1: L = features[ids] @ W + b   (M=8192, N=256, K=256, fp32)
// 64x128 tile, 128 threads, 4m x 16n microtile (32 FFMA2/thread/k).
//  - A pre-duplicated in smem as {a,a} pairs: 2 LDS.128 per thread-k yield 4
//    packed f32x2 A operands directly (no dup MOVs). 4 distinct 16B addrs per
//    warp -> 1 crossbar cyc each.
//  - B mapping tx=tid&7, four float4 groups at n=32j+tx*4: each LDS.128 has 8
//    distinct quads = exactly 128B -> 1 crossbar cyc (4-way lane dup).
//  Per block per k: smem 24 cyc << FMA 64 cyc; issue 38/warp << 64 busy.
//  B filled via cp.async, A via register prefetch + dup-store. Double buffer.
// ---------------------------------------------------------------------------
__global__ void __launch_bounds__(NT) linear_kernel(
    const int*   __restrict__ ids,
    const float* __restrict__ features,
    const float* __restrict__ W,
    const float* __restrict__ b)
{
    __shared__ float As[2][BK][ADST];   // duplicated A pairs, 33.8 KB
    __shared__ float Bs[2][BK][BN];     // 32 KB
    __shared__ int   rowid[BM];

    const int tid = threadIdx.x;
    const int tx  = tid & 7;            // n: cols 32j + tx*4 .. +3, j=0..3
    const int ty  = tid >> 3;           // m: rows ty*4 .. +3  (0..15)
    const int m0  = blockIdx.x * BM;
    const int n0  = blockIdx.y * BN;

    if (tid < BM) rowid[tid] = ids[m0 + tid];
    __syncthreads();

    // A fill: each thread owns row ar, 16 consecutive k at offset ah.
    const int ar = tid >> 1;
    const int ah = (tid & 1) * 16;
    const size_t rowA = (size_t)rowid[ar] * NODE_DIM + ah;

    // B fill: 8 cp.async of 16B; k-rows bkr+4j, cols bc..bc+3.
    const int bkr = tid >> 5;           // 0..3
    const int bc  = (tid & 31) * 4;
    const float* Wb = W + n0 + bc;

    unsigned long long acc[4][8];
#pragma unroll
    for (int i = 0; i < 4; i++)
#pragma unroll
        for (int j = 0; j < 8; j++) acc[i][j] = 0ull;

    float4 pa[4];

    // ---- Prologue: fill chunk 0 ----
#pragma unroll
    for (int c4 = 0; c4 < 4; c4++)
        pa[c4] = *(const float4*)&features[rowA + c4 * 4];
#pragma unroll
    for (int c4 = 0; c4 < 4; c4++) {
        const float e[4] = {pa[c4].x, pa[c4].y, pa[c4].z, pa[c4].w};
#pragma unroll
        for (int q = 0; q < 4; q++)
            *(float2*)&As[0][ah + c4 * 4 + q][2 * ar] = make_float2(e[q], e[q]);
    }
#pragma unroll
    for (int j = 0; j < 8; j++) {
        const unsigned sm = (unsigned)__cvta_generic_to_shared(
            &Bs[0][bkr + 4 * j][bc]);
        CP_ASYNC16(sm, &Wb[(size_t)(bkr + 4 * j) * NODE_DIM]);
    }
    CP_COMMIT();
    CP_WAIT0();
    __syncthreads();

    int buf = 0;
#pragma unroll
    for (int c = 0; c < NCHUNK; c++) {
        if (c + 1 < NCHUNK) {
            const int kc = (c + 1) * BK;
#pragma unroll
            for (int c4 = 0; c4 < 4; c4++)
                pa[c4] = *(const float4*)&features[rowA + kc + c4 * 4];
#pragma unroll
            for (int j = 0; j < 8; j++) {
                const unsigned sm = (unsigned)__cvta_generic_to_shared(
                    &Bs[buf ^ 1][bkr + 4 * j][bc]);
                CP_ASYNC16(sm, &Wb[(size_t)(kc + bkr + 4 * j) * NODE_DIM]);
            }
            CP_COMMIT();
        }

#pragma unroll
        for (int k = 0; k < BK; k++) {
            // A: 4 packed rows in 2 LDS.128 (already {a,a} duplicated).
            const ulonglong2 aP0 = *(const ulonglong2*)&As[buf][k][2 * (ty * 4)];
            const ulonglong2 aP1 = *(const ulonglong2*)&As[buf][k][2 * (ty * 4 + 2)];
            // B: 4 groups, each exactly 128B distinct per warp.
            const ulonglong2 b0 = *(const ulonglong2*)&Bs[buf][k][tx * 4];
            const ulonglong2 b1 = *(const ulonglong2*)&Bs[buf][k][32 + tx * 4];
            const ulonglong2 b2 = *(const ulonglong2*)&Bs[buf][k][64 + tx * 4];
            const ulonglong2 b3 = *(const ulonglong2*)&Bs[buf][k][96 + tx * 4];

            FMA2(acc[0][0], aP0.x, b0.x); FMA2(acc[0][1], aP0.x, b0.y);
            FMA2(acc[0][2], aP0.x, b1.x); FMA2(acc[0][3], aP0.x, b1.y);
            FMA2(acc[0][4], aP0.x, b2.x); FMA2(acc[0][5], aP0.x, b2.y);
            FMA2(acc[0][6], aP0.x, b3.x); FMA2(acc[0][7], aP0.x, b3.y);

            FMA2(acc[1][0], aP0.y, b0.x); FMA2(acc[1][1], aP0.y, b0.y);
            FMA2(acc[1][2], aP0.y, b1.x); FMA2(acc[1][3], aP0.y, b1.y);
            FMA2(acc[1][4], aP0.y, b2.x); FMA2(acc[1][5], aP0.y, b2.y);
            FMA2(acc[1][6], aP0.y, b3.x); FMA2(acc[1][7], aP0.y, b3.y);

            FMA2(acc[2][0], aP1.x, b0.x); FMA2(acc[2][1], aP1.x, b0.y);
            FMA2(acc[2][2], aP1.x, b1.x); FMA2(acc[2][3], aP1.x, b1.y);
            FMA2(acc[2][4], aP1.x, b2.x); FMA2(acc[2][5], aP1.x, b2.y);
            FMA2(acc[2][6], aP1.x, b3.x); FMA2(acc[2][7], aP1.x, b3.y);

            FMA2(acc[3][0], aP1.y, b0.x); FMA2(acc[3][1], aP1.y, b0.y);
            FMA2(acc[3][2], aP1.y, b1.x); FMA2(acc[3][3], aP1.y, b1.y);
            FMA2(acc[3][4], aP1.y, b2.x); FMA2(acc[3][5], aP1.y, b2.y);
            FMA2(acc[3][6], aP1.y, b3.x); FMA2(acc[3][7], aP1.y, b3.y);
        }

        if (c + 1 < NCHUNK) {
            const int nb = buf ^ 1;
#pragma unroll
            for (int c4 = 0; c4 < 4; c4++) {
                const float e[4] = {pa[c4].x, pa[c4].y, pa[c4].z, pa[c4].w};
#pragma unroll
                for (int q = 0; q < 4; q++)
                    *(float2*)&As[nb][ah + c4 * 4 + q][2 * ar] =
                        make_float2(e[q], e[q]);
            }
            CP_WAIT0();
        }
        __syncthreads();
        buf ^= 1;
    }

    // Epilogue: 4 rows x 4 float4 groups, + bias.
#pragma unroll
    for (int j = 0; j < 4; j++) {
        const float4 bias = *(const float4*)&b[n0 + 32 * j + tx * 4];
#pragma unroll
        for (int i = 0; i < 4; i++) {
            const float2 lo = unpack_f32x2(acc[i][2 * j]);
            const float2 hi = unpack_f32x2(acc[i][2 * j + 1]);
            float4 o;
            o.x = lo.x + bias.x;  o.y = lo.y + bias.y;
            o.z = hi.x + bias.z;  o.w = hi.y + bias.w;
            const int m = m0 + ty * 4 + i;
            *(float4*)&g_L[(size_t)m * NODE_DIM + n0 + 32 * j + tx * 4] = o;
        }
    }
}

// ---------------------------------------------------------------------------
// Kernel 2: per-v neighbor scoring + grouped argmin + outputs (unchanged:
// 32 regs, ~94% occ — at the aggregate L2 gather wall, ~45 us floor).
//
// Output layout (float32):
//   [0,            131072)  sel  (node ids, exact in fp32)
//   [131072,       262144)  att  (all 1.0)
//   [262144,       270336)  numnz
//   [270336,       278528)  numnz (duplicate)
// ---------------------------------------------------------------------------
__global__ void __launch_bounds__(256) sampler_kernel(
    const int*   __restrict__ ids,
    const int*   __restrict__ adj,
    const float* __restrict__ features,
    float*       __restrict__ out)
{
    __shared__ float ls[NODE_DIM];
    __shared__ float scores[MAX_DEG];
    __shared__ int   nbr[MAX_DEG];
    __shared__ float flags[NUM_SAMPLES];

    const int v    = blockIdx.x;
    const int tid  = threadIdx.x;
    const int lane = tid & 31;
    const int w    = tid >> 5;

    const int vid = __ldg(&ids[v]);

    ls[tid] = g_L[(size_t)v * NODE_DIM + tid];
    if (tid < MAX_DEG) nbr[tid] = adj[(size_t)vid * MAX_DEG + tid];
    __syncthreads();

    const float4 lv0 = ((const float4*)ls)[lane];
    const float4 lv1 = ((const float4*)ls)[lane + 32];

#pragma unroll
    for (int t = 0; t < 8; t++) {
        const int k  = w * 8 + t;
        const int nb = nbr[k];
        const float4* fr = (const float4*)(features + (size_t)nb * NODE_DIM);
        const float4 f0 = __ldg(&fr[lane]);
        const float4 f1 = __ldg(&fr[lane + 32]);

        float s = f0.x * lv0.x + f0.y * lv0.y + f0.z * lv0.z + f0.w * lv0.w
                + f1.x * lv1.x + f1.y * lv1.y + f1.z * lv1.z + f1.w * lv1.w;

#pragma unroll
        for (int off = 16; off > 0; off >>= 1)
            s += __shfl_xor_sync(0xffffffffu, s, off);

        if (lane == 0) scores[k] = fmaxf(s, 0.0f);
    }
    __syncthreads();

    if (tid < NUM_SAMPLES) {
        const int base = tid * GROUP_DIM;
        float m  = scores[base];
        int   bi = 0;
#pragma unroll
        for (int g = 1; g < GROUP_DIM; g++) {
            float sc = scores[base + g];
            if (sc < m) { m = sc; bi = g; }       // strict <  => first min
        }
        const int sid = nbr[base + bi];
        out[(size_t)v * NUM_SAMPLES + tid]                          = (float)sid;
        out[(size_t)V_TOTAL * NUM_SAMPLES + v * NUM_SAMPLES + tid]  = 1.0f;
        flags[tid] = (sid == N_NODES - 1) ? 0.0f : 1.0f;
    }
    __syncthreads();

    if (tid == 0) {
        float nn = 0.0f;
#pragma unroll
        for (int s = 0; s < NUM_SAMPLES; s++) nn += flags[s];
        out[2 * V_TOTAL * NUM_SAMPLES + v]           = nn;
        out[2 * V_TOTAL * NUM_SAMPLES + V_TOTAL + v] = nn;
    }
}

extern "C" void kernel_launch(void* const* d_in, const int* in_sizes, int n_in,
                              void* d_out, int out_size)
{
    const int*   ids      = (const int*)  d_in[0];
    const int*   adj      = (const int*)  d_in[1];
    const float* features = (const float*)d_in[2];
    const float* W        = (const float*)d_in[3];
    const float* b        = (const float*)d_in[4];
    float*       out      = (float*)d_out;

    linear_kernel<<<dim3(V_TOTAL / BM, NODE_DIM / BN), NT>>>(ids, features, W, b);
    sampler_kernel<<<V_TOTAL, 256>>>(ids, adj, features, out);
}

// round 8
// speedup vs baseline: 1.2179x; 1.2179x over previous
#include <cuda_runtime.h>

#define V_TOTAL     8192
#define NODE_DIM    256
#define MAX_DEG     64
#define NUM_SAMPLES 16
#define GROUP_DIM   4
#define N_NODES     100000

#define BM 64
#define BN 128
#define BK 32
#define NCHUNK (NODE_DIM / BK)   // 8
#define ADST (2 * BM + 4)        // 132 floats: rows 16B-aligned

// Scratch for linear-branch result L = features[ids] @ W + b   (8 MB)
__device__ float g_L[V_TOTAL * NODE_DIM];

// Packed fp32x2 FMA (Blackwell): d = a*b + d, two fp32 lanes per instruction.
#define FMA2(d, a, b) \
    asm("fma.rn.f32x2 %0, %1, %2, %0;" : "+l"(d) : "l"(a), "l"(b))

static __device__ __forceinline__ float2 unpack_f32x2(unsigned long long v) {
    float2 r;
    asm("mov.b64 {%0, %1}, %2;" : "=f"(r.x), "=f"(r.y) : "l"(v));
    return r;
}

// ---------------------------------------------------------------------------
// Kernel 1: L = features[ids] @ W + b   (M=8192, N=256, K=256, fp32)
// R4 geometry (proven 25.4us): 64x128 tile, 256 threads, 4x8 microtile,
// grid (128,2)=256 blocks, double-buffered, register prefetch.
// R7 delta: A stored PRE-DUPLICATED as {a,a} float2 pairs. Inner loop reads
// A with 2 broadcast LDS.128 (2 distinct addrs/warp -> 1 crossbar cyc each),
// yielding 4 packed f32x2 operands with ZERO dup-MOVs.
// Per warp per k: 4 LDS + 16 FFMA2 = 20 issues vs 32 FMA-busy cyc (slack);
// per-SM crossbar 48 cyc vs FMA 64 cyc (slack). B path identical to R4
// (LDS.128 at tx*4 / 64+tx*4, conflict-free).
// ---------------------------------------------------------------------------
__global__ void __launch_bounds__(256) linear_kernel(
    const int*   __restrict__ ids,
    const float* __restrict__ features,
    const float* __restrict__ W,
    const float* __restrict__ b)
{
    __shared__ float As[2][BK][ADST];   // duplicated A pairs, 33.8 KB
    __shared__ float Bs[2][BK][BN];     // 32 KB
    __shared__ int   rowid[BM];

    const int tid = threadIdx.x;
    const int tx  = tid & 15;          // n-dir: cols tx*4..+3 and 64+tx*4..+3
    const int ty  = tid >> 4;          // m-dir: 16 threads * 4 rows
    const int m0  = blockIdx.x * BM;
    const int n0  = blockIdx.y * BN;

    if (tid < BM) rowid[tid] = ids[m0 + tid];
    __syncthreads();

    // Fill decomposition (same as R4). A: 2 float4/thread. B: 4 float4/thread.
    const int ar  = tid >> 3;          // A rows ar, ar+32
    const int ac  = (tid & 7) * 4;     // k-offset within chunk
    const int bkr = tid >> 5;          // B k-rows bkr, bkr+8, bkr+16, bkr+24
    const int bc  = (tid & 31) * 4;

    const size_t rowA0 = (size_t)rowid[ar]      * NODE_DIM;
    const size_t rowA1 = (size_t)rowid[ar + 32] * NODE_DIM;
    const float* Wb = W + n0 + bc;

    unsigned long long acc[4][4];
#pragma unroll
    for (int i = 0; i < 4; i++)
#pragma unroll
        for (int j = 0; j < 4; j++) acc[i][j] = 0ull;

    // ---- Prologue: fill chunk 0 ----
    {
        const float4 a0 = *(const float4*)&features[rowA0 + ac];
        const float4 a1 = *(const float4*)&features[rowA1 + ac];
        const float e0[4] = {a0.x, a0.y, a0.z, a0.w};
        const float e1[4] = {a1.x, a1.y, a1.z, a1.w};
#pragma unroll
        for (int q = 0; q < 4; q++) {
            *(float2*)&As[0][ac + q][2 * ar]        = make_float2(e0[q], e0[q]);
            *(float2*)&As[0][ac + q][2 * (ar + 32)] = make_float2(e1[q], e1[q]);
        }
#pragma unroll
        for (int j = 0; j < 4; j++)
            *(float4*)&Bs[0][bkr + 8 * j][bc] =
                *(const float4*)&Wb[(size_t)(bkr + 8 * j) * NODE_DIM];
    }
    __syncthreads();

    int buf = 0;
#pragma unroll
    for (int c = 0; c < NCHUNK; c++) {
        float4 pa0, pa1, pb[4];
        if (c + 1 < NCHUNK) {
            const int kc = (c + 1) * BK;
            pa0 = *(const float4*)&features[rowA0 + kc + ac];
            pa1 = *(const float4*)&features[rowA1 + kc + ac];
#pragma unroll
            for (int j = 0; j < 4; j++)
                pb[j] = *(const float4*)&Wb[(size_t)(kc + bkr + 8 * j) * NODE_DIM];
        }

#pragma unroll
        for (int k = 0; k < BK; k++) {
            // A: 4 packed rows via 2 broadcast LDS.128 (pre-duplicated).
            const ulonglong2 aP0 = *(const ulonglong2*)&As[buf][k][8 * ty];
            const ulonglong2 aP1 = *(const ulonglong2*)&As[buf][k][8 * ty + 4];
            // B: conflict-free (phase addresses tx*16B hit each bank once).
            const ulonglong2 b01 = *(const ulonglong2*)&Bs[buf][k][tx * 4];
            const ulonglong2 b23 = *(const ulonglong2*)&Bs[buf][k][64 + tx * 4];

            FMA2(acc[0][0], aP0.x, b01.x); FMA2(acc[0][1], aP0.x, b01.y);
            FMA2(acc[0][2], aP0.x, b23.x); FMA2(acc[0][3], aP0.x, b23.y);
            FMA2(acc[1][0], aP0.y, b01.x); FMA2(acc[1][1], aP0.y, b01.y);
            FMA2(acc[1][2], aP0.y, b23.x); FMA2(acc[1][3], aP0.y, b23.y);
            FMA2(acc[2][0], aP1.x, b01.x); FMA2(acc[2][1], aP1.x, b01.y);
            FMA2(acc[2][2], aP1.x, b23.x); FMA2(acc[2][3], aP1.x, b23.y);
            FMA2(acc[3][0], aP1.y, b01.x); FMA2(acc[3][1], aP1.y, b01.y);
            FMA2(acc[3][2], aP1.y, b23.x); FMA2(acc[3][3], aP1.y, b23.y);
        }

        if (c + 1 < NCHUNK) {
            const int nb = buf ^ 1;
            const float e0[4] = {pa0.x, pa0.y, pa0.z, pa0.w};
            const float e1[4] = {pa1.x, pa1.y, pa1.z, pa1.w};
#pragma unroll
            for (int q = 0; q < 4; q++) {
                *(float2*)&As[nb][ac + q][2 * ar]        = make_float2(e0[q], e0[q]);
                *(float2*)&As[nb][ac + q][2 * (ar + 32)] = make_float2(e1[q], e1[q]);
            }
#pragma unroll
            for (int j = 0; j < 4; j++)
                *(float4*)&Bs[nb][bkr + 8 * j][bc] = pb[j];
        }
        __syncthreads();
        buf ^= 1;
    }

    const float4 bias0 = *(const float4*)&b[n0 + tx * 4];
    const float4 bias1 = *(const float4*)&b[n0 + 64 + tx * 4];
#pragma unroll
    for (int i = 0; i < 4; i++) {
        const float2 p0 = unpack_f32x2(acc[i][0]);
        const float2 p1 = unpack_f32x2(acc[i][1]);
        const float2 p2 = unpack_f32x2(acc[i][2]);
        const float2 p3 = unpack_f32x2(acc[i][3]);
        float4 o0, o1;
        o0.x = p0.x + bias0.x;  o0.y = p0.y + bias0.y;
        o0.z = p1.x + bias0.z;  o0.w = p1.y + bias0.w;
        o1.x = p2.x + bias1.x;  o1.y = p2.y + bias1.y;
        o1.z = p3.x + bias1.z;  o1.w = p3.y + bias1.w;
        const int m = m0 + ty * 4 + i;
        *(float4*)&g_L[(size_t)m * NODE_DIM + n0 + tx * 4]      = o0;
        *(float4*)&g_L[(size_t)m * NODE_DIM + n0 + 64 + tx * 4] = o1;
    }
}

// ---------------------------------------------------------------------------
// Kernel 2: per-v neighbor scoring + grouped argmin + outputs (unchanged:
// 32 regs, ~93% occ — at the aggregate L2 gather wall, ~45 us floor).
//
// Output layout (float32):
//   [0,            131072)  sel  (node ids, exact in fp32)
//   [131072,       262144)  att  (all 1.0)
//   [262144,       270336)  numnz
//   [270336,       278528)  numnz (duplicate)
// ---------------------------------------------------------------------------
__global__ void __launch_bounds__(256) sampler_kernel(
    const int*   __restrict__ ids,
    const int*   __restrict__ adj,
    const float* __restrict__ features,
    float*       __restrict__ out)
{
    __shared__ float ls[NODE_DIM];
    __shared__ float scores[MAX_DEG];
    __shared__ int   nbr[MAX_DEG];
    __shared__ float flags[NUM_SAMPLES];

    const int v    = blockIdx.x;
    const int tid  = threadIdx.x;
    const int lane = tid & 31;
    const int w    = tid >> 5;

    const int vid = __ldg(&ids[v]);

    ls[tid] = g_L[(size_t)v * NODE_DIM + tid];
    if (tid < MAX_DEG) nbr[tid] = adj[(size_t)vid * MAX_DEG + tid];
    __syncthreads();

    const float4 lv0 = ((const float4*)ls)[lane];
    const float4 lv1 = ((const float4*)ls)[lane + 32];

#pragma unroll
    for (int t = 0; t < 8; t++) {
        const int k  = w * 8 + t;
        const int nb = nbr[k];
        const float4* fr = (const float4*)(features + (size_t)nb * NODE_DIM);
        const float4 f0 = __ldg(&fr[lane]);
        const float4 f1 = __ldg(&fr[lane + 32]);

        float s = f0.x * lv0.x + f0.y * lv0.y + f0.z * lv0.z + f0.w * lv0.w
                + f1.x * lv1.x + f1.y * lv1.y + f1.z * lv1.z + f1.w * lv1.w;

#pragma unroll
        for (int off = 16; off > 0; off >>= 1)
            s += __shfl_xor_sync(0xffffffffu, s, off);

        if (lane == 0) scores[k] = fmaxf(s, 0.0f);
    }
    __syncthreads();

    if (tid < NUM_SAMPLES) {
        const int base = tid * GROUP_DIM;
        float m  = scores[base];
        int   bi = 0;
#pragma unroll
        for (int g = 1; g < GROUP_DIM; g++) {
            float sc = scores[base + g];
            if (sc < m) { m = sc; bi = g; }       // strict <  => first min
        }
        const int sid = nbr[base + bi];
        out[(size_t)v * NUM_SAMPLES + tid]                          = (float)sid;
        out[(size_t)V_TOTAL * NUM_SAMPLES + v * NUM_SAMPLES + tid]  = 1.0f;
        flags[tid] = (sid == N_NODES - 1) ? 0.0f : 1.0f;
    }
    __syncthreads();

    if (tid == 0) {
        float nn = 0.0f;
#pragma unroll
        for (int s = 0; s < NUM_SAMPLES; s++) nn += flags[s];
        out[2 * V_TOTAL * NUM_SAMPLES + v]           = nn;
        out[2 * V_TOTAL * NUM_SAMPLES + V_TOTAL + v] = nn;
    }
}

extern "C" void kernel_launch(void* const* d_in, const int* in_sizes, int n_in,
                              void* d_out, int out_size)
{
    const int*   ids      = (const int*)  d_in[0];
    const int*   adj      = (const int*)  d_in[1];
    const float* features = (const float*)d_in[2];
    const float* W        = (const float*)d_in[3];
    const float* b        = (const float*)d_in[4];
    float*       out      = (float*)d_out;

    linear_kernel<<<dim3(V_TOTAL / BM, NODE_DIM / BN), 256>>>(ids, features, W, b);
    sampler_kernel<<<V_TOTAL, 256>>>(ids, adj, features, out);
}